// round 6
// baseline (speedup 1.0000x reference)
#include <cuda_runtime.h>
#include <cstdint>
#include <math.h>

#define NLEV  16
#define BIN_R 64
#define NBINS (BIN_R * BIN_R * BIN_R)      // 262144
#define MAXB  2097152

struct LevelMeta {
    float    scale;   // np.float32(16*exp(i*log(s)) - 1)
    uint32_t res;     // encode resolution = ceil(f32 scale)+1
    uint32_t res2;    // res*res
    uint32_t size;    // padded, capped map size (entries)
    uint32_t offset;  // cumulative offset in entries (float2 units)
    uint32_t hashed;  // 1 => hash path, 0 => dense path
    uint32_t pad0, pad1;
};

__device__ LevelMeta g_meta[NLEV];
__device__ uint32_t  g_hist[NBINS];
__device__ uint32_t  g_bsum[256];
__device__ int       g_pid[MAXB];         // sorted-order -> original id
__device__ float     g_spos[MAXB * 3];    // positions in sorted order

// ---------------------------------------------------------------------------
// Level metadata, computed on device in fp64 exactly as the numpy reference.
// ---------------------------------------------------------------------------
__global__ void setup_meta_kernel() {
    if (threadIdx.x != 0 || blockIdx.x != 0) return;
    const double s  = 1.3195079565048218;
    const double ls = log(s);
    uint64_t off = 0;
    for (int i = 0; i < NLEV; ++i) {
        double  t       = exp((double)i * ls);
        double  scale_d = 16.0 * t - 1.0;
        float   scale_f = (float)scale_d;
        uint32_t res_meta = (uint32_t)ceil(scale_d) + 1u;   // _level_meta: f64 ceil
        uint32_t res_enc  = (uint32_t)ceilf(scale_f) + 1u;  // _encode: f32 ceil
        uint64_t p = (uint64_t)res_meta * res_meta * res_meta;
        if (p % 8ull) p = ((p + 7ull) / 8ull) * 8ull;
        uint64_t sz = p < 524288ull ? p : 524288ull;        // min(MAX_PARAMS, p)
        uint32_t indicator =
            ((uint64_t)res_meta * res_meta * res_meta <= sz) ? 1u : 0u;
        LevelMeta m;
        m.scale  = scale_f;
        m.res    = res_enc;
        m.res2   = res_enc * res_enc;
        m.size   = (uint32_t)sz;
        m.offset = (uint32_t)off;
        m.hashed = indicator ? 0u : 1u;
        m.pad0 = 0; m.pad1 = 0;
        g_meta[i] = m;
        off += sz;
    }
}

// ---------------------------------------------------------------------------
// Counting sort of points into 64^3 spatial bins.
// Only affects gather locality; per-point output is order-independent.
// ---------------------------------------------------------------------------
__device__ __forceinline__ int bin_of(float x, float y, float z) {
    int bx = (int)(x * (float)BIN_R);
    int by = (int)(y * (float)BIN_R);
    int bz = (int)(z * (float)BIN_R);
    bx = min(BIN_R - 1, max(0, bx));
    by = min(BIN_R - 1, max(0, by));
    bz = min(BIN_R - 1, max(0, bz));
    return (bz << 12) | (by << 6) | bx;
}

__global__ void zero_hist_kernel() {
    int g = blockIdx.x * 256 + threadIdx.x;            // 256 blocks x 256 thr
    reinterpret_cast<uint4*>(g_hist)[g] = make_uint4(0u, 0u, 0u, 0u);
}

__global__ void hist_kernel(const float* __restrict__ pos, int B) {
    int i = blockIdx.x * blockDim.x + threadIdx.x;
    if (i >= B) return;
    atomicAdd(&g_hist[bin_of(pos[3*i], pos[3*i+1], pos[3*i+2])], 1u);
}

// 256 blocks x 1024 threads: per-block exclusive scan (Hillis-Steele).
__global__ void scan_block_kernel() {
    __shared__ uint32_t s[1024];
    const int t = threadIdx.x;
    const int g = blockIdx.x * 1024 + t;
    const uint32_t v = g_hist[g];
    s[t] = v;
    __syncthreads();
    #pragma unroll
    for (int off = 1; off < 1024; off <<= 1) {
        uint32_t u = (t >= off) ? s[t - off] : 0u;
        __syncthreads();
        s[t] += u;
        __syncthreads();
    }
    g_hist[g] = s[t] - v;                  // exclusive prefix within block
    if (t == 1023) g_bsum[blockIdx.x] = s[t];
}

__global__ void scan_top_kernel() {
    __shared__ uint32_t s[256];
    const int t = threadIdx.x;
    const uint32_t v = g_bsum[t];
    s[t] = v;
    __syncthreads();
    #pragma unroll
    for (int off = 1; off < 256; off <<= 1) {
        uint32_t u = (t >= off) ? s[t - off] : 0u;
        __syncthreads();
        s[t] += u;
        __syncthreads();
    }
    g_bsum[t] = s[t] - v;                  // exclusive over block sums
}

__global__ void add_back_kernel() {
    int g = blockIdx.x * 1024 + threadIdx.x;
    if (g < NBINS) g_hist[g] += g_bsum[blockIdx.x];
}

// Scatter: claims slot via atomic, writes id AND position in sorted order so
// the encode kernel's loads are fully coalesced.
__global__ void scatter_kernel(const float* __restrict__ pos, int B) {
    int i = blockIdx.x * blockDim.x + threadIdx.x;
    if (i >= B) return;
    const float x = pos[3*i], y = pos[3*i+1], z = pos[3*i+2];
    int b = bin_of(x, y, z);
    uint32_t p = atomicAdd(&g_hist[b], 1u);
    if (p < (uint32_t)B) {
        g_pid[p] = i;
        g_spos[3*p + 0] = x;
        g_spos[3*p + 1] = y;
        g_spos[3*p + 2] = z;
    }
}

// ---------------------------------------------------------------------------
// Encode. Block: 32 (spatially sorted) points x 16 levels (512 threads).
// warp = 32 adjacent points at one level -> lanes share table cache lines.
// ---------------------------------------------------------------------------
__global__ __launch_bounds__(512)
void hashenc_kernel(const float* __restrict__ table,
                    float*       __restrict__ out,
                    int B)
{
    __shared__ int    spid[32];        // original point ids (sorted order)
    __shared__ float  sp[96];          // 32 points * xyz (sorted order)
    __shared__ float2 sout[32][17];    // [point][level], padded

    const int b0  = blockIdx.x << 5;
    const int tid = threadIdx.x;

    if (tid < 32) {
        spid[tid] = (b0 + tid < B) ? g_pid[b0 + tid] : 0;
    }
    if (tid < 96) {
        long long gi = (long long)b0 * 3 + tid;
        sp[tid] = (gi < (long long)B * 3) ? g_spos[gi] : 0.0f;
    }
    __syncthreads();

    const int x   = tid & 31;   // point within block
    const int lev = tid >> 5;   // level (uniform per warp)

    const LevelMeta m = g_meta[lev];

    const float px = sp[x * 3 + 0];
    const float py = sp[x * 3 + 1];
    const float pz = sp[x * 3 + 2];

    // pos*scale + 0.5 with NO fma contraction (match XLA mul-then-add)
    const float qx = __fadd_rn(__fmul_rn(px, m.scale), 0.5f);
    const float qy = __fadd_rn(__fmul_rn(py, m.scale), 0.5f);
    const float qz = __fadd_rn(__fmul_rn(pz, m.scale), 0.5f);

    const float flx = floorf(qx), fly = floorf(qy), flz = floorf(qz);
    const float fx = __fsub_rn(qx, flx);
    const float fy = __fsub_rn(qy, fly);
    const float fz = __fsub_rn(qz, flz);
    const uint32_t gx = (uint32_t)(int)flx;
    const uint32_t gy = (uint32_t)(int)fly;
    const uint32_t gz = (uint32_t)(int)flz;

    const float wx0 = 1.0f - fx, wx1 = fx;
    const float wy0 = 1.0f - fy, wy1 = fy;
    const float wz0 = 1.0f - fz, wz1 = fz;

    uint32_t idxs[8];
    if (m.hashed) {
        const uint32_t mask = m.size - 1u;   // hashed levels: size == 2^19
        const uint32_t hx0 = gx;
        const uint32_t hx1 = gx + 1u;
        const uint32_t hy0 = gy * 2654435761u;
        const uint32_t hy1 = hy0 + 2654435761u;
        const uint32_t hz0 = gz * 805459861u;
        const uint32_t hz1 = hz0 + 805459861u;
        idxs[0] = (hx0 ^ hy0 ^ hz0) & mask;
        idxs[1] = (hx1 ^ hy0 ^ hz0) & mask;
        idxs[2] = (hx0 ^ hy1 ^ hz0) & mask;
        idxs[3] = (hx1 ^ hy1 ^ hz0) & mask;
        idxs[4] = (hx0 ^ hy0 ^ hz1) & mask;
        idxs[5] = (hx1 ^ hy0 ^ hz1) & mask;
        idxs[6] = (hx0 ^ hy1 ^ hz1) & mask;
        idxs[7] = (hx1 ^ hy1 ^ hz1) & mask;
    } else {
        // dense: h = x + y*res + z*res^2, then h % size with h < 2*size
        const uint32_t cy0 = gy * m.res;
        const uint32_t cy1 = cy0 + m.res;
        const uint32_t cz0 = gz * m.res2;
        const uint32_t cz1 = cz0 + m.res2;
        const uint32_t sz  = m.size;
        uint32_t h;
        h = gx      + cy0 + cz0; idxs[0] = h - (h >= sz ? sz : 0u);
        h = gx + 1u + cy0 + cz0; idxs[1] = h - (h >= sz ? sz : 0u);
        h = gx      + cy1 + cz0; idxs[2] = h - (h >= sz ? sz : 0u);
        h = gx + 1u + cy1 + cz0; idxs[3] = h - (h >= sz ? sz : 0u);
        h = gx      + cy0 + cz1; idxs[4] = h - (h >= sz ? sz : 0u);
        h = gx + 1u + cy0 + cz1; idxs[5] = h - (h >= sz ? sz : 0u);
        h = gx      + cy1 + cz1; idxs[6] = h - (h >= sz ? sz : 0u);
        h = gx + 1u + cy1 + cz1; idxs[7] = h - (h >= sz ? sz : 0u);
    }

    const float2* __restrict__ t2 =
        reinterpret_cast<const float2*>(table) + m.offset;

    float acc0 = 0.0f, acc1 = 0.0f;
    {
        const float2 f0 = __ldg(&t2[idxs[0]]);
        const float2 f1 = __ldg(&t2[idxs[1]]);
        const float2 f2 = __ldg(&t2[idxs[2]]);
        const float2 f3 = __ldg(&t2[idxs[3]]);
        const float2 f4 = __ldg(&t2[idxs[4]]);
        const float2 f5 = __ldg(&t2[idxs[5]]);
        const float2 f6 = __ldg(&t2[idxs[6]]);
        const float2 f7 = __ldg(&t2[idxs[7]]);

        const float w0 = wx0 * wy0 * wz0;
        const float w1 = wx1 * wy0 * wz0;
        const float w2 = wx0 * wy1 * wz0;
        const float w3 = wx1 * wy1 * wz0;
        const float w4 = wx0 * wy0 * wz1;
        const float w5 = wx1 * wy0 * wz1;
        const float w6 = wx0 * wy1 * wz1;
        const float w7 = wx1 * wy1 * wz1;

        acc0 = fmaf(w0, f0.x, acc0); acc1 = fmaf(w0, f0.y, acc1);
        acc0 = fmaf(w1, f1.x, acc0); acc1 = fmaf(w1, f1.y, acc1);
        acc0 = fmaf(w2, f2.x, acc0); acc1 = fmaf(w2, f2.y, acc1);
        acc0 = fmaf(w3, f3.x, acc0); acc1 = fmaf(w3, f3.y, acc1);
        acc0 = fmaf(w4, f4.x, acc0); acc1 = fmaf(w4, f4.y, acc1);
        acc0 = fmaf(w5, f5.x, acc0); acc1 = fmaf(w5, f5.y, acc1);
        acc0 = fmaf(w6, f6.x, acc0); acc1 = fmaf(w6, f6.y, acc1);
        acc0 = fmaf(w7, f7.x, acc0); acc1 = fmaf(w7, f7.y, acc1);
    }

    sout[x][lev] = make_float2(acc0, acc1);
    __syncthreads();

    // Write each point's 16 float2 to its ORIGINAL slot (128B per point).
    const int p = tid >> 4;
    if (b0 + p < B) {
        const int l = tid & 15;
        reinterpret_cast<float2*>(out)[(size_t)spid[p] * 16 + l] = sout[p][l];
    }
}

extern "C" void kernel_launch(void* const* d_in, const int* in_sizes, int n_in,
                              void* d_out, int out_size) {
    const float* positions = (const float*)d_in[0];
    const float* table     = (const float*)d_in[1];
    float*       out       = (float*)d_out;
    int B = in_sizes[0] / 3;
    if (B > MAXB) B = MAXB;

    setup_meta_kernel<<<1, 1>>>();

    // counting sort into 64^3 spatial bins
    zero_hist_kernel<<<256, 256>>>();
    hist_kernel<<<(B + 1023) / 1024, 1024>>>(positions, B);
    scan_block_kernel<<<256, 1024>>>();
    scan_top_kernel<<<1, 256>>>();
    add_back_kernel<<<NBINS / 1024, 1024>>>();
    scatter_kernel<<<(B + 1023) / 1024, 1024>>>(positions, B);

    const int nblocks = (B + 31) / 32;
    hashenc_kernel<<<nblocks, 512>>>(table, out, B);
}

// round 7
// speedup vs baseline: 1.0426x; 1.0426x over previous
#include <cuda_runtime.h>
#include <cstdint>
#include <math.h>

#define NLEV  16
#define BIN_R 64
#define NBINS (BIN_R * BIN_R * BIN_R)      // 262144
#define MAXB  2097152

struct LevelMeta {
    float    scale;   // np.float32(16*exp(i*log(s)) - 1)
    uint32_t res;     // encode resolution = ceil(f32 scale)+1
    uint32_t res2;    // res*res
    uint32_t size;    // padded, capped map size (entries)
    uint32_t offset;  // cumulative offset in entries (float2 units)
    uint32_t hashed;  // 1 => hash path, 0 => dense path
    uint32_t pad0, pad1;
};

__device__ LevelMeta g_meta[NLEV];
__device__ uint32_t  g_hist[NBINS];
__device__ uint32_t  g_bsum[256];
__device__ int       g_perm[MAXB];        // sorted-order -> original id

// ---------------------------------------------------------------------------
// Fused init: zero the bin histogram (vectorized) and, on one thread, compute
// level metadata in fp64 exactly as the numpy reference.
// Launch: 256 blocks x 256 threads (65536 threads x uint4 = 262144 words).
// ---------------------------------------------------------------------------
__global__ void init_kernel() {
    const int g = blockIdx.x * 256 + threadIdx.x;
    reinterpret_cast<uint4*>(g_hist)[g] = make_uint4(0u, 0u, 0u, 0u);

    if (g == 0) {
        const double s  = 1.3195079565048218;
        const double ls = log(s);
        uint64_t off = 0;
        for (int i = 0; i < NLEV; ++i) {
            double  t       = exp((double)i * ls);
            double  scale_d = 16.0 * t - 1.0;
            float   scale_f = (float)scale_d;
            uint32_t res_meta = (uint32_t)ceil(scale_d) + 1u;   // _level_meta: f64 ceil
            uint32_t res_enc  = (uint32_t)ceilf(scale_f) + 1u;  // _encode: f32 ceil
            uint64_t p = (uint64_t)res_meta * res_meta * res_meta;
            if (p % 8ull) p = ((p + 7ull) / 8ull) * 8ull;
            uint64_t sz = p < 524288ull ? p : 524288ull;        // min(MAX_PARAMS, p)
            uint32_t indicator =
                ((uint64_t)res_meta * res_meta * res_meta <= sz) ? 1u : 0u;
            LevelMeta m;
            m.scale  = scale_f;
            m.res    = res_enc;
            m.res2   = res_enc * res_enc;
            m.size   = (uint32_t)sz;
            m.offset = (uint32_t)off;
            m.hashed = indicator ? 0u : 1u;
            m.pad0 = 0; m.pad1 = 0;
            g_meta[i] = m;
            off += sz;
        }
    }
}

// ---------------------------------------------------------------------------
// Counting sort of point ids into 64^3 spatial bins.
// Only affects gather locality; per-point output is order-independent.
// ---------------------------------------------------------------------------
__device__ __forceinline__ int bin_of(float x, float y, float z) {
    int bx = (int)(x * (float)BIN_R);
    int by = (int)(y * (float)BIN_R);
    int bz = (int)(z * (float)BIN_R);
    bx = min(BIN_R - 1, max(0, bx));
    by = min(BIN_R - 1, max(0, by));
    bz = min(BIN_R - 1, max(0, bz));
    return (bz << 12) | (by << 6) | bx;
}

__global__ void hist_kernel(const float* __restrict__ pos, int B) {
    int i = blockIdx.x * blockDim.x + threadIdx.x;
    if (i >= B) return;
    atomicAdd(&g_hist[bin_of(pos[3*i], pos[3*i+1], pos[3*i+2])], 1u);
}

// 256 blocks x 1024 threads: per-block exclusive scan (Hillis-Steele).
__global__ void scan_block_kernel() {
    __shared__ uint32_t s[1024];
    const int t = threadIdx.x;
    const int g = blockIdx.x * 1024 + t;
    const uint32_t v = g_hist[g];
    s[t] = v;
    __syncthreads();
    #pragma unroll
    for (int off = 1; off < 1024; off <<= 1) {
        uint32_t u = (t >= off) ? s[t - off] : 0u;
        __syncthreads();
        s[t] += u;
        __syncthreads();
    }
    g_hist[g] = s[t] - v;                  // exclusive prefix within block
    if (t == 1023) g_bsum[blockIdx.x] = s[t];
}

// add_back with the 256-wide top-level scan fused in: every block loads the
// 256 block sums, computes the exclusive prefix for its own blockIdx, and
// adds it to its 1024 hist entries. 256 blocks x 1024 threads.
__global__ void add_back_kernel() {
    __shared__ uint32_t s[256];
    __shared__ uint32_t prefix;
    const int t = threadIdx.x;
    if (t < 256) s[t] = g_bsum[t];
    __syncthreads();
    if (t < 256) {
        // simple smem scan over 256 (cheap, runs on every block)
        #pragma unroll
        for (int off = 1; off < 256; off <<= 1) {
            uint32_t u = (t >= off) ? s[t - off] : 0u;
            __syncthreads();
            s[t] += u;
            __syncthreads();
        }
        if (t == (int)blockIdx.x)
            prefix = s[t] - g_bsum[t];     // exclusive prefix for this block
    } else {
        #pragma unroll
        for (int off = 1; off < 256; off <<= 1) { __syncthreads(); __syncthreads(); }
    }
    __syncthreads();
    g_hist[blockIdx.x * 1024 + t] += prefix;
}

// Scatter: claim slot via atomic, write original id in sorted order.
__global__ void scatter_kernel(const float* __restrict__ pos, int B) {
    int i = blockIdx.x * blockDim.x + threadIdx.x;
    if (i >= B) return;
    int b = bin_of(pos[3*i], pos[3*i+1], pos[3*i+2]);
    uint32_t p = atomicAdd(&g_hist[b], 1u);
    if (p < (uint32_t)B) g_perm[p] = i;
}

// ---------------------------------------------------------------------------
// Encode. Block: 32 (spatially sorted) points x 16 levels (512 threads).
// warp = 32 adjacent points at one level -> lanes share table cache lines.
// ---------------------------------------------------------------------------
__global__ __launch_bounds__(512)
void hashenc_kernel(const float* __restrict__ positions,
                    const float* __restrict__ table,
                    float*       __restrict__ out,
                    int B)
{
    __shared__ int    spid[32];        // original point ids (sorted order)
    __shared__ float  sp[96];          // 32 points * xyz
    __shared__ float2 sout[32][17];    // [point][level], padded

    const int b0  = blockIdx.x << 5;
    const int tid = threadIdx.x;

    if (tid < 32) {
        spid[tid] = (b0 + tid < B) ? g_perm[b0 + tid] : 0;
    }
    __syncthreads();
    if (tid < 96) {
        sp[tid] = positions[(size_t)spid[tid / 3] * 3 + (tid % 3)];
    }
    __syncthreads();

    const int x   = tid & 31;   // point within block
    const int lev = tid >> 5;   // level (uniform per warp)

    const LevelMeta m = g_meta[lev];

    const float px = sp[x * 3 + 0];
    const float py = sp[x * 3 + 1];
    const float pz = sp[x * 3 + 2];

    // pos*scale + 0.5 with NO fma contraction (match XLA mul-then-add)
    const float qx = __fadd_rn(__fmul_rn(px, m.scale), 0.5f);
    const float qy = __fadd_rn(__fmul_rn(py, m.scale), 0.5f);
    const float qz = __fadd_rn(__fmul_rn(pz, m.scale), 0.5f);

    const float flx = floorf(qx), fly = floorf(qy), flz = floorf(qz);
    const float fx = __fsub_rn(qx, flx);
    const float fy = __fsub_rn(qy, fly);
    const float fz = __fsub_rn(qz, flz);
    const uint32_t gx = (uint32_t)(int)flx;
    const uint32_t gy = (uint32_t)(int)fly;
    const uint32_t gz = (uint32_t)(int)flz;

    const float wx0 = 1.0f - fx, wx1 = fx;
    const float wy0 = 1.0f - fy, wy1 = fy;
    const float wz0 = 1.0f - fz, wz1 = fz;

    uint32_t idxs[8];
    if (m.hashed) {
        const uint32_t mask = m.size - 1u;   // hashed levels: size == 2^19
        const uint32_t hx0 = gx;
        const uint32_t hx1 = gx + 1u;
        const uint32_t hy0 = gy * 2654435761u;
        const uint32_t hy1 = hy0 + 2654435761u;
        const uint32_t hz0 = gz * 805459861u;
        const uint32_t hz1 = hz0 + 805459861u;
        idxs[0] = (hx0 ^ hy0 ^ hz0) & mask;
        idxs[1] = (hx1 ^ hy0 ^ hz0) & mask;
        idxs[2] = (hx0 ^ hy1 ^ hz0) & mask;
        idxs[3] = (hx1 ^ hy1 ^ hz0) & mask;
        idxs[4] = (hx0 ^ hy0 ^ hz1) & mask;
        idxs[5] = (hx1 ^ hy0 ^ hz1) & mask;
        idxs[6] = (hx0 ^ hy1 ^ hz1) & mask;
        idxs[7] = (hx1 ^ hy1 ^ hz1) & mask;
    } else {
        // dense: h = x + y*res + z*res^2, then h % size with h < 2*size
        const uint32_t cy0 = gy * m.res;
        const uint32_t cy1 = cy0 + m.res;
        const uint32_t cz0 = gz * m.res2;
        const uint32_t cz1 = cz0 + m.res2;
        const uint32_t sz  = m.size;
        uint32_t h;
        h = gx      + cy0 + cz0; idxs[0] = h - (h >= sz ? sz : 0u);
        h = gx + 1u + cy0 + cz0; idxs[1] = h - (h >= sz ? sz : 0u);
        h = gx      + cy1 + cz0; idxs[2] = h - (h >= sz ? sz : 0u);
        h = gx + 1u + cy1 + cz0; idxs[3] = h - (h >= sz ? sz : 0u);
        h = gx      + cy0 + cz1; idxs[4] = h - (h >= sz ? sz : 0u);
        h = gx + 1u + cy0 + cz1; idxs[5] = h - (h >= sz ? sz : 0u);
        h = gx      + cy1 + cz1; idxs[6] = h - (h >= sz ? sz : 0u);
        h = gx + 1u + cy1 + cz1; idxs[7] = h - (h >= sz ? sz : 0u);
    }

    const float2* __restrict__ t2 =
        reinterpret_cast<const float2*>(table) + m.offset;

    float acc0 = 0.0f, acc1 = 0.0f;
    {
        const float2 f0 = __ldg(&t2[idxs[0]]);
        const float2 f1 = __ldg(&t2[idxs[1]]);
        const float2 f2 = __ldg(&t2[idxs[2]]);
        const float2 f3 = __ldg(&t2[idxs[3]]);
        const float2 f4 = __ldg(&t2[idxs[4]]);
        const float2 f5 = __ldg(&t2[idxs[5]]);
        const float2 f6 = __ldg(&t2[idxs[6]]);
        const float2 f7 = __ldg(&t2[idxs[7]]);

        const float w0 = wx0 * wy0 * wz0;
        const float w1 = wx1 * wy0 * wz0;
        const float w2 = wx0 * wy1 * wz0;
        const float w3 = wx1 * wy1 * wz0;
        const float w4 = wx0 * wy0 * wz1;
        const float w5 = wx1 * wy0 * wz1;
        const float w6 = wx0 * wy1 * wz1;
        const float w7 = wx1 * wy1 * wz1;

        acc0 = fmaf(w0, f0.x, acc0); acc1 = fmaf(w0, f0.y, acc1);
        acc0 = fmaf(w1, f1.x, acc0); acc1 = fmaf(w1, f1.y, acc1);
        acc0 = fmaf(w2, f2.x, acc0); acc1 = fmaf(w2, f2.y, acc1);
        acc0 = fmaf(w3, f3.x, acc0); acc1 = fmaf(w3, f3.y, acc1);
        acc0 = fmaf(w4, f4.x, acc0); acc1 = fmaf(w4, f4.y, acc1);
        acc0 = fmaf(w5, f5.x, acc0); acc1 = fmaf(w5, f5.y, acc1);
        acc0 = fmaf(w6, f6.x, acc0); acc1 = fmaf(w6, f6.y, acc1);
        acc0 = fmaf(w7, f7.x, acc0); acc1 = fmaf(w7, f7.y, acc1);
    }

    sout[x][lev] = make_float2(acc0, acc1);
    __syncthreads();

    // Write each point's 16 float2 to its ORIGINAL slot (128B per point).
    const int p = tid >> 4;
    if (b0 + p < B) {
        const int l = tid & 15;
        reinterpret_cast<float2*>(out)[(size_t)spid[p] * 16 + l] = sout[p][l];
    }
}

extern "C" void kernel_launch(void* const* d_in, const int* in_sizes, int n_in,
                              void* d_out, int out_size) {
    const float* positions = (const float*)d_in[0];
    const float* table     = (const float*)d_in[1];
    float*       out       = (float*)d_out;
    int B = in_sizes[0] / 3;
    if (B > MAXB) B = MAXB;

    init_kernel<<<256, 256>>>();
    hist_kernel<<<(B + 1023) / 1024, 1024>>>(positions, B);
    scan_block_kernel<<<256, 1024>>>();
    add_back_kernel<<<256, 1024>>>();
    scatter_kernel<<<(B + 1023) / 1024, 1024>>>(positions, B);

    const int nblocks = (B + 31) / 32;
    hashenc_kernel<<<nblocks, 512>>>(positions, table, out, B);
}